// round 8
// baseline (speedup 1.0000x reference)
#include <cuda_runtime.h>
#include <cuda_bf16.h>

#define THREADS 256
#define BPSM    6
#define NB      (148 * BPSM)      // 888 blocks, all co-resident
#define NWARP   (THREADS / 32)
#define MAXB    64
#define GCAP    1184              // groups staged in s_z: 18944 B
#define CH_G    128               // groups per staging chunk
#define CH_P    (CH_G * 4)        // 512 points per chunk
#define CBYTES  (CH_G * 48)       // 6144 B coord per chunk
#define SBYTES  (CH_G * 16)       // 2048 B seg per chunk
#define STAGEB  (CBYTES + SBYTES) // 8192 B per buffer

// ---------------- device scratch (zero-init; no allocations) ----------------
__device__ unsigned d_ag[MAXB];    // max ord(z) | seg==0   (0 => none)
__device__ unsigned d_ap[MAXB];    // max ~ord(z) | seg==1  (0 => none)
__device__ unsigned d_azm[MAXB];   // max ~ord(z) overall
__device__ unsigned d_azx[MAXB];   // max ord(z) overall
__device__ float    d_part[NB];
__device__ unsigned d_c1, d_c2;

__device__ __forceinline__ unsigned ordf(float f) {
    unsigned u = __float_as_uint(f);
    return (u & 0x80000000u) ? ~u : (u | 0x80000000u);
}
__device__ __forceinline__ float deordf(unsigned o) {
    unsigned u = (o & 0x80000000u) ? (o & 0x7FFFFFFFu) : ~o;
    return __uint_as_float(u);
}
__device__ __forceinline__ float packzs(float z, int s) {
    return __uint_as_float((__float_as_uint(z) & ~1u) | (unsigned)(s & 1));
}
__device__ __forceinline__ unsigned smem_u32(const void* p) {
    return (unsigned)__cvta_generic_to_shared(p);
}
__device__ __forceinline__ void mbar_init(unsigned mb, unsigned cnt) {
    asm volatile("mbarrier.init.shared.b64 [%0], %1;" :: "r"(mb), "r"(cnt) : "memory");
}
__device__ __forceinline__ void mbar_inval(unsigned mb) {
    asm volatile("mbarrier.inval.shared.b64 [%0];" :: "r"(mb) : "memory");
}
__device__ __forceinline__ void mbar_expect_tx(unsigned mb, unsigned bytes) {
    asm volatile("mbarrier.arrive.expect_tx.shared.b64 _, [%0], %1;"
                 :: "r"(mb), "r"(bytes) : "memory");
}
__device__ __forceinline__ void bulk_g2s(unsigned dst, const void* src,
                                         unsigned bytes, unsigned mb) {
    asm volatile(
        "cp.async.bulk.shared::cluster.global.mbarrier::complete_tx::bytes "
        "[%0], [%1], %2, [%3];"
        :: "r"(dst), "l"(src), "r"(bytes), "r"(mb) : "memory");
}
__device__ __forceinline__ void mbar_wait(unsigned mb, unsigned parity) {
    asm volatile(
        "{\n\t.reg .pred P;\n\t"
        "WL_%=:\n\t"
        "mbarrier.try_wait.parity.acquire.cta.shared::cta.b64 P, [%0], %1, 0x989680;\n\t"
        "@P bra WD_%=;\n\t"
        "bra WL_%=;\n\t"
        "WD_%=:\n\t}"
        :: "r"(mb), "r"(parity) : "memory");
}

// focal-CE * gaussian weight; seg bit in z mantissa LSB. 3 MUFU.
__device__ __forceinline__ float pointTermZ(float p0, float p1, float z, float mu)
{
    int s = __float_as_uint(z) & 1;
    float tgt = s ? p1 : p0;
    float oth = s ? p0 : p1;
    float v   = oth - tgt;
    float nav = fminf(v, -v);
    float e;  asm("ex2.approx.f32 %0,%1;" : "=f"(e)  : "f"(1.4426950409f * nav));
    float l2; asm("lg2.approx.f32 %0,%1;" : "=f"(l2) : "f"(1.0f + e));
    float sp = fmaxf(v, 0.0f) + 0.69314718056f * l2;   // -log p_t
    float d  = z - mu;
    float dd = d * d;
    float cf = (d <= 0.0f) ? -72.13475204f : -4.50842200f;
    float ew = (d > 0.8f) ? -3.32192809f : cf * dd;
    float ex = fmaf(2.8853900818f, fminf(v, 0.0f), fmaf(-2.0f, l2, ew));
    float sgw; asm("ex2.approx.f32 %0,%1;" : "=f"(sgw) : "f"(ex));
    return sp * sgw;
}

// ================= single fused persistent kernel (bulk-staged) =================
template <bool SMEMZ>
__global__ void __launch_bounds__(THREADS, BPSM) k_fused(
    const float4* __restrict__ pred4, const float* __restrict__ pred,
    const float4* __restrict__ coord4, const float* __restrict__ coord,
    const int4* __restrict__ seg4, const int* __restrict__ segment,
    const int* __restrict__ offset, int n, int B, int gpb, float* __restrict__ out)
{
    __shared__ __align__(16) char s_stage[2][STAGEB];
    __shared__ float    s_z[GCAP * 4];
    __shared__ __align__(8) unsigned long long s_mb[2];
    __shared__ int      s_off[MAXB];
    __shared__ float    s_mu[MAXB];
    __shared__ unsigned s_g[MAXB], s_p[MAXB], s_m[MAXB], s_x[MAXB];
    __shared__ float    s_w[NWARP];
    __shared__ bool     s_last;

    int t = threadIdx.x;
    int bid = blockIdx.x;
    int lane = t & 31, warp = t >> 5;

    unsigned mb0 = smem_u32(&s_mb[0]);
    unsigned mb1 = smem_u32(&s_mb[1]);
    unsigned st0 = smem_u32(&s_stage[0][0]);
    unsigned st1 = smem_u32(&s_stage[1][0]);

    for (int j = t; j < B; j += THREADS) {
        s_g[j] = 0u; s_p[j] = 0u; s_m[j] = 0u; s_x[j] = 0u;
        s_off[j] = offset[j];
    }
    if (SMEMZ && t == 0) { mbar_init(mb0, 1); mbar_init(mb1, 1); }
    __syncthreads();

    int n4 = n >> 2;
    int g0 = bid * gpb;
    int g1 = min(g0 + gpb, n4);
    int cnt = g1 - g0;                 // groups this block
    int cnt4 = cnt << 2;               // points this block (excl. global tail)
    int gp0 = g0 << 2;                 // first point index
    bool isLast = (bid == NB - 1);
    int tail0 = n4 << 2;

    int b0 = 0, b1 = 0;
    bool uni = true;
    if (cnt > 0 || (isLast && tail0 < n)) {
        int p0 = min(gp0, n - 1);
        int pe = isLast ? (n - 1) : (gp0 + cnt4 - 1);
        while (p0 >= s_off[b0]) b0++;
        b1 = b0; while (pe >= s_off[b1]) b1++;
        uni = (b0 == b1);
    }

    unsigned uses0 = 0, uses1 = 0;
    int nch = (cnt + CH_G - 1) / CH_G;

    // ===================== phase A =====================
    if (SMEMZ) {
        auto issueA = [&](int k) {
            if (t != 0) return;
            int pbase = k * CH_P;
            int pts = min(CH_P, cnt4 - pbase);
            unsigned cby = (unsigned)pts * 12u;
            unsigned sby = (unsigned)pts * 4u;
            unsigned mb  = (k & 1) ? mb1 : mb0;
            unsigned dst = (k & 1) ? st1 : st0;
            const char* srcc = (const char*)coord + (size_t)(gp0 + pbase) * 12;
            const char* srcs = (const char*)segment + (size_t)(gp0 + pbase) * 4;
            mbar_expect_tx(mb, cby + sby);
            bulk_g2s(dst, srcc, cby, mb);
            bulk_g2s(dst + CBYTES, srcs, sby, mb);
        };
        if (nch > 0) issueA(0);
        if (nch > 1) issueA(1);

        unsigned lg = 0u, lp = 0u, lzm = 0u, lzx = 0u;
        int cur = b0;
        for (int k = 0; k < nch; k++) {
            int bsel = k & 1;
            unsigned mb = bsel ? mb1 : mb0;
            unsigned par = (bsel ? uses1 : uses0) & 1u;
            mbar_wait(mb, par);
            if (bsel) uses1++; else uses0++;

            int pbase = k * CH_P;
            int pts = min(CH_P, cnt4 - pbase);
            const char* cb = s_stage[bsel];
            const int*  sb = (const int*)(s_stage[bsel] + CBYTES);

            if (uni) {
                for (int p = t; p < pts; p += THREADS) {
                    float z = *(const float*)(cb + p * 12 + 8);
                    int sv = sb[p];
                    unsigned o = ordf(z);
                    lzx = max(lzx, o); lzm = max(lzm, ~o);
                    if (sv) lp = max(lp, ~o); else lg = max(lg, o);
                    s_z[pbase + p] = packzs(z, sv);
                }
            } else {
                for (int p = t; p < pts; p += THREADS) {
                    float z = *(const float*)(cb + p * 12 + 8);
                    int sv = sb[p];
                    int i = gp0 + pbase + p;
                    while (i >= s_off[cur]) cur++;
                    unsigned o = ordf(z);
                    atomicMax(&s_m[cur], ~o);
                    atomicMax(&s_x[cur], o);
                    if (sv) atomicMax(&s_p[cur], ~o);
                    else    atomicMax(&s_g[cur], o);
                    s_z[pbase + p] = packzs(z, sv);
                }
            }
            __syncthreads();
            if (k + 2 < nch) issueA(k + 2);
        }
        if (uni) {
            #pragma unroll
            for (int o = 16; o > 0; o >>= 1) {
                lzm = max(lzm, __shfl_xor_sync(~0u, lzm, o));
                lzx = max(lzx, __shfl_xor_sync(~0u, lzx, o));
                lg  = max(lg,  __shfl_xor_sync(~0u, lg,  o));
                lp  = max(lp,  __shfl_xor_sync(~0u, lp,  o));
            }
            if (lane == 0 && cnt > 0) {
                atomicMax(&s_m[b0], lzm);
                atomicMax(&s_x[b0], lzx);
                atomicMax(&s_g[b0], lg);
                atomicMax(&s_p[b0], lp);
            }
        }
    } else {
        // fallback: direct LDG (R7 path)
        if (cnt > 0) {
            if (uni) {
                unsigned lg = 0u, lp = 0u, lzm = 0u, lzx = 0u;
                for (int g = g0 + t; g < g1; g += THREADS) {
                    float4 a  = coord4[3 * g + 0];
                    float4 bb = coord4[3 * g + 1];
                    float4 c  = coord4[3 * g + 2];
                    int4   s  = seg4[g];
                    unsigned o0 = ordf(a.z), o1 = ordf(bb.y), o2 = ordf(c.x), o3 = ordf(c.w);
                    lzx = max(lzx, max(max(o0, o1), max(o2, o3)));
                    lzm = max(lzm, max(max(~o0, ~o1), max(~o2, ~o3)));
                    lg  = max(lg, max(max(s.x ? 0u : o0, s.y ? 0u : o1),
                                      max(s.z ? 0u : o2, s.w ? 0u : o3)));
                    lp  = max(lp, max(max(s.x ? ~o0 : 0u, s.y ? ~o1 : 0u),
                                      max(s.z ? ~o2 : 0u, s.w ? ~o3 : 0u)));
                }
                #pragma unroll
                for (int o = 16; o > 0; o >>= 1) {
                    lzm = max(lzm, __shfl_xor_sync(~0u, lzm, o));
                    lzx = max(lzx, __shfl_xor_sync(~0u, lzx, o));
                    lg  = max(lg,  __shfl_xor_sync(~0u, lg,  o));
                    lp  = max(lp,  __shfl_xor_sync(~0u, lp,  o));
                }
                if (lane == 0) {
                    atomicMax(&s_m[b0], lzm); atomicMax(&s_x[b0], lzx);
                    atomicMax(&s_g[b0], lg);  atomicMax(&s_p[b0], lp);
                }
            } else {
                int cur = b0;
                for (int g = g0 + t; g < g1; g += THREADS) {
                    float4 a  = coord4[3 * g + 0];
                    float4 bb = coord4[3 * g + 1];
                    float4 c  = coord4[3 * g + 2];
                    int4   s  = seg4[g];
                    int i0 = g << 2;
                    float zz[4] = {a.z, bb.y, c.x, c.w};
                    int   ss[4] = {s.x, s.y, s.z, s.w};
                    #pragma unroll
                    for (int q = 0; q < 4; q++) {
                        int i = i0 + q;
                        while (i >= s_off[cur]) cur++;
                        unsigned o = ordf(zz[q]);
                        atomicMax(&s_m[cur], ~o);
                        atomicMax(&s_x[cur], o);
                        if (ss[q]) atomicMax(&s_p[cur], ~o);
                        else       atomicMax(&s_g[cur], o);
                    }
                }
            }
        }
    }

    // global tail points (n % 4) — last block, from gmem
    if (isLast) {
        for (int i = tail0 + t; i < n; i += THREADS) {
            int b = 0; while (i >= s_off[b]) b++;
            unsigned o = ordf(coord[3 * i + 2]);
            atomicMax(&s_m[b], ~o);
            atomicMax(&s_x[b], o);
            if (segment[i]) atomicMax(&s_p[b], ~o);
            else            atomicMax(&s_g[b], o);
        }
    }

    __syncthreads();
    for (int j = t; j < B; j += THREADS) {
        if (s_g[j]) atomicMax(&d_ag[j],  s_g[j]);
        if (s_p[j]) atomicMax(&d_ap[j],  s_p[j]);
        if (s_m[j]) atomicMax(&d_azm[j], s_m[j]);
        if (s_x[j]) atomicMax(&d_azx[j], s_x[j]);
    }
    __threadfence();
    __syncthreads();
    if (t == 0) {
        atomicAdd(&d_c1, 1u);
        while (*(volatile unsigned*)&d_c1 < (unsigned)NB) { __nanosleep(128); }
    }
    __syncthreads();
    __threadfence();

    for (int j = t; j < B; j += THREADS) {
        unsigned ag  = __ldcg(&d_ag[j]);
        unsigned ap  = __ldcg(&d_ap[j]);
        unsigned azm = __ldcg(&d_azm[j]);
        unsigned azx = __ldcg(&d_azx[j]);
        float g = ag ? deordf(ag)  : deordf(~azm);
        float p = ap ? deordf(~ap) : deordf(azx);
        s_mu[j] = g + (p - g) * 0.5f;
    }
    __syncthreads();

    // ===================== phase B =====================
    float acc = 0.0f;
    float muu = s_mu[b0];

    if (SMEMZ) {
        auto issueB = [&](int k) {
            if (t != 0) return;
            int pbase = k * CH_P;
            int pts = min(CH_P, cnt4 - pbase);
            unsigned by = (unsigned)pts * 8u;
            unsigned mb  = (k & 1) ? mb1 : mb0;
            unsigned dst = (k & 1) ? st1 : st0;
            const char* src = (const char*)pred + (size_t)(gp0 + pbase) * 8;
            mbar_expect_tx(mb, by);
            bulk_g2s(dst, src, by, mb);
        };
        if (nch > 0) issueB(0);
        if (nch > 1) issueB(1);

        int cur = b0;
        for (int k = 0; k < nch; k++) {
            int bsel = k & 1;
            unsigned mb = bsel ? mb1 : mb0;
            unsigned par = (bsel ? uses1 : uses0) & 1u;
            mbar_wait(mb, par);
            if (bsel) uses1++; else uses0++;

            int pbase = k * CH_P;
            int pts = min(CH_P, cnt4 - pbase);
            const char* pb = s_stage[bsel];

            if (uni) {
                for (int p = t; p < pts; p += THREADS) {
                    float2 pp = *(const float2*)(pb + p * 8);
                    float z = s_z[pbase + p];
                    acc += pointTermZ(pp.x, pp.y, z, muu);
                }
            } else {
                for (int p = t; p < pts; p += THREADS) {
                    float2 pp = *(const float2*)(pb + p * 8);
                    float z = s_z[pbase + p];
                    int i = gp0 + pbase + p;
                    while (i >= s_off[cur]) cur++;
                    acc += pointTermZ(pp.x, pp.y, z, s_mu[cur]);
                }
            }
            __syncthreads();
            if (k + 2 < nch) issueB(k + 2);
        }
    } else {
        if (cnt > 0) {
            int cur = b0;
            for (int g = g0 + t; g < g1; g += THREADS) {
                float4 pa = pred4[2 * g + 0];
                float4 pb = pred4[2 * g + 1];
                float4 a  = coord4[3 * g + 0];
                float4 bb = coord4[3 * g + 1];
                float4 c  = coord4[3 * g + 2];
                int4   s  = seg4[g];
                float4 zs = make_float4(packzs(a.z, s.x), packzs(bb.y, s.y),
                                        packzs(c.x, s.z), packzs(c.w, s.w));
                float m0 = muu, m1 = muu, m2 = muu, m3 = muu;
                if (!uni) {
                    int i0 = g << 2;
                    while (i0 >= s_off[cur]) cur++;
                    int q1 = cur; while (i0 + 1 >= s_off[q1]) q1++;
                    int q2 = q1;  while (i0 + 2 >= s_off[q2]) q2++;
                    int q3 = q2;  while (i0 + 3 >= s_off[q3]) q3++;
                    m0 = s_mu[cur]; m1 = s_mu[q1]; m2 = s_mu[q2]; m3 = s_mu[q3];
                }
                acc += pointTermZ(pa.x, pa.y, zs.x, m0);
                acc += pointTermZ(pa.z, pa.w, zs.y, m1);
                acc += pointTermZ(pb.x, pb.y, zs.z, m2);
                acc += pointTermZ(pb.z, pb.w, zs.w, m3);
            }
        }
    }

    if (isLast) {
        for (int i = tail0 + t; i < n; i += THREADS) {
            int b = 0; while (i >= s_off[b]) b++;
            acc += pointTermZ(pred[2 * i], pred[2 * i + 1],
                              packzs(coord[3 * i + 2], segment[i]), s_mu[b]);
        }
    }

    #pragma unroll
    for (int o = 16; o > 0; o >>= 1) acc += __shfl_xor_sync(~0u, acc, o);
    if (lane == 0) s_w[warp] = acc;
    __syncthreads();
    if (t == 0) {
        float tot = 0.0f;
        #pragma unroll
        for (int w = 0; w < NWARP; w++) tot += s_w[w];
        d_part[bid] = tot;
        __threadfence();
        s_last = (atomicAdd(&d_c2, 1u) == NB - 1);
    }
    __syncthreads();

    if (s_last) {
        double* s_d = reinterpret_cast<double*>(s_z);
        double da = 0.0;
        for (int i = t; i < NB; i += THREADS) da += (double)d_part[i];
        s_d[t] = da;
        __syncthreads();
        for (int s = THREADS / 2; s > 0; s >>= 1) {
            if (t < s) s_d[t] += s_d[t + s];
            __syncthreads();
        }
        for (int j = t; j < B; j += THREADS) {
            d_ag[j] = 0u; d_ap[j] = 0u; d_azm[j] = 0u; d_azx[j] = 0u;
        }
        if (t == 0) {
            out[0] = (float)(s_d[0] / (double)n);
            d_c1 = 0u; d_c2 = 0u;
        }
    }

    if (SMEMZ) {
        __syncthreads();
        if (t == 0) { mbar_inval(mb0); mbar_inval(mb1); }
    }
}

// ---------------- launch ----------------
extern "C" void kernel_launch(void* const* d_in, const int* in_sizes, int n_in,
                              void* d_out, int out_size)
{
    const float* pred    = (const float*)d_in[0];
    const float* coord   = (const float*)d_in[1];
    const int*   segment = (const int*)d_in[2];
    const int*   offset  = (const int*)d_in[3];
    int n = in_sizes[2];
    int B = in_sizes[3];
    if (B > MAXB) B = MAXB;
    if (B < 1) B = 1;

    int n4 = n >> 2;
    int gpb = (n4 + NB - 1) / NB;
    if (gpb < 1) gpb = 1;
    bool smemz = (gpb <= GCAP) && (n >= 4);

    if (smemz) {
        k_fused<true><<<NB, THREADS>>>((const float4*)pred, pred,
                                       (const float4*)coord, coord,
                                       (const int4*)segment, segment,
                                       offset, n, B, gpb, (float*)d_out);
    } else {
        k_fused<false><<<NB, THREADS>>>((const float4*)pred, pred,
                                        (const float4*)coord, coord,
                                        (const int4*)segment, segment,
                                        offset, n, B, gpb, (float*)d_out);
    }
}

// round 10
// speedup vs baseline: 1.0719x; 1.0719x over previous
#include <cuda_runtime.h>
#include <cuda_bf16.h>

#define THREADS 256
#define BPSM    6
#define NB      (148 * BPSM)      // 888 blocks, all co-resident
#define NWARP   (THREADS / 32)
#define MAXB    64
#define GCAP    1184              // groups (4 pts) staged in smem: 18944 B

// ---------------- device scratch (zero-init; no allocations) ----------------
__device__ unsigned d_ag[MAXB];    // max ord(z) | seg==0   (0 => none)
__device__ unsigned d_ap[MAXB];    // max ~ord(z) | seg==1  (0 => none)
__device__ unsigned d_azm[MAXB];   // max ~ord(z) overall
__device__ unsigned d_azx[MAXB];   // max ord(z) overall
__device__ float    d_part[NB];
__device__ unsigned d_c1, d_c2;

__device__ __forceinline__ unsigned ordf(float f) {
    unsigned u = __float_as_uint(f);
    return (u & 0x80000000u) ? ~u : (u | 0x80000000u);
}
__device__ __forceinline__ float deordf(unsigned o) {
    unsigned u = (o & 0x80000000u) ? (o & 0x7FFFFFFFu) : ~o;
    return __uint_as_float(u);
}
__device__ __forceinline__ float packzs(float z, int s) {
    return __uint_as_float((__float_as_uint(z) & ~1u) | (unsigned)(s & 1));
}

// focal-CE * gaussian weight; segment bit in z's mantissa LSB. 3 MUFU.
__device__ __forceinline__ float pointTermZ(float p0, float p1, float z, float mu)
{
    int s = __float_as_uint(z) & 1;
    float tgt = s ? p1 : p0;
    float oth = s ? p0 : p1;
    float v   = oth - tgt;
    float nav = fminf(v, -v);                          // -|v|
    float e;  asm("ex2.approx.f32 %0,%1;" : "=f"(e)  : "f"(1.4426950409f * nav));
    float l2; asm("lg2.approx.f32 %0,%1;" : "=f"(l2) : "f"(1.0f + e));
    float sp = fmaxf(v, 0.0f) + 0.69314718056f * l2;   // -log p_t
    float d  = z - mu;
    float dd = d * d;
    float cf = (d <= 0.0f) ? -72.13475204f : -4.50842200f;  // log2-scaled coeffs
    float ew = (d > 0.8f) ? -3.32192809f : cf * dd;          // log2(0.1) clamp
    float ex = fmaf(2.8853900818f, fminf(v, 0.0f), fmaf(-2.0f, l2, ew));
    float sgw; asm("ex2.approx.f32 %0,%1;" : "=f"(sgw) : "f"(ex));
    return sp * sgw;
}

// ================= single fused persistent kernel =================
template <bool SMEMZ>
__global__ void __launch_bounds__(THREADS, BPSM) k_fused(
    const float4* __restrict__ pred4, const float* __restrict__ pred,
    const float4* __restrict__ coord4, const float* __restrict__ coord,
    const int4* __restrict__ seg4, const int* __restrict__ segment,
    const int* __restrict__ offset, int n, int B, int gpb, float* __restrict__ out)
{
    __shared__ float    s_z[GCAP * 4];        // 18944 B packed z+seg
    __shared__ int      s_off[MAXB];
    __shared__ float    s_mu[MAXB];
    __shared__ unsigned s_g[MAXB], s_p[MAXB], s_m[MAXB], s_x[MAXB];
    __shared__ float    s_w[NWARP];
    __shared__ bool     s_last;

    int t = threadIdx.x;
    int bid = blockIdx.x;
    int lane = t & 31, warp = t >> 5;

    for (int j = t; j < B; j += THREADS) {
        s_g[j] = 0u; s_p[j] = 0u; s_m[j] = 0u; s_x[j] = 0u;
        s_off[j] = offset[j];
    }
    __syncthreads();

    int n4 = n >> 2;
    int g0 = bid * gpb;
    int g1 = min(g0 + gpb, n4);
    int cnt4 = (g1 - g0) << 2;
    bool isLast = (bid == NB - 1);
    int tail0 = n4 << 2;
    bool hasWork = (g0 < g1) || (isLast && tail0 < n);

    // ---- prefetch this block's pred range into L2 (overlaps with phase A) ----
    {
        const char* pbase = (const char*)pred + (size_t)(g0 << 2) * 8;
        int bytes = cnt4 * 8;
        for (int off = t * 128; off < bytes; off += THREADS * 128) {
            asm volatile("prefetch.global.L2 [%0];" :: "l"(pbase + off));
        }
    }

    int b0 = 0, b1 = 0;
    bool uni = true;

    // ===================== phase A: z reductions (+ stage z in smem) =====================
    if (hasWork) {
        int p0 = min(g0 << 2, n - 1);
        int pe = isLast ? (n - 1) : ((g1 << 2) - 1);
        while (p0 >= s_off[b0]) b0++;
        b1 = b0; while (pe >= s_off[b1]) b1++;
        uni = (b0 == b1);

        if (uni) {
            unsigned lg = 0u, lp = 0u, lzm = 0u, lzx = 0u;   // all max, identity 0
            for (int g = g0 + t; g < g1; g += THREADS) {
                float4 a  = __ldcs(coord4 + 3 * g + 0);
                float4 bb = __ldcs(coord4 + 3 * g + 1);
                float4 c  = __ldcs(coord4 + 3 * g + 2);
                int4   s  = __ldcs(seg4 + g);
                if (SMEMZ) {
                    float4 zv = make_float4(packzs(a.z, s.x), packzs(bb.y, s.y),
                                            packzs(c.x, s.z), packzs(c.w, s.w));
                    *reinterpret_cast<float4*>(s_z + ((g - g0) << 2)) = zv;
                }
                unsigned o0 = ordf(a.z), o1 = ordf(bb.y), o2 = ordf(c.x), o3 = ordf(c.w);
                lzx = max(lzx, max(max(o0, o1), max(o2, o3)));
                lzm = max(lzm, max(max(~o0, ~o1), max(~o2, ~o3)));
                lg  = max(lg, max(max(s.x ? 0u : o0, s.y ? 0u : o1),
                                  max(s.z ? 0u : o2, s.w ? 0u : o3)));
                lp  = max(lp, max(max(s.x ? ~o0 : 0u, s.y ? ~o1 : 0u),
                                  max(s.z ? ~o2 : 0u, s.w ? ~o3 : 0u)));
            }
            if (isLast) {
                for (int i = tail0 + t; i < n; i += THREADS) {
                    unsigned o = ordf(coord[3 * i + 2]);
                    if (segment[i]) lp = max(lp, ~o); else lg = max(lg, o);
                    lzm = max(lzm, ~o); lzx = max(lzx, o);
                }
            }
            #pragma unroll
            for (int o = 16; o > 0; o >>= 1) {
                lzm = max(lzm, __shfl_xor_sync(~0u, lzm, o));
                lzx = max(lzx, __shfl_xor_sync(~0u, lzx, o));
                lg  = max(lg,  __shfl_xor_sync(~0u, lg,  o));
                lp  = max(lp,  __shfl_xor_sync(~0u, lp,  o));
            }
            if (lane == 0) {
                atomicMax(&s_m[b0], lzm);
                atomicMax(&s_x[b0], lzx);
                atomicMax(&s_g[b0], lg);
                atomicMax(&s_p[b0], lp);
            }
        } else {
            // straddle block (<= B-1 of them): per-point smem atomics
            for (int g = g0 + t; g < g1; g += THREADS) {
                float4 a  = __ldcs(coord4 + 3 * g + 0);
                float4 bb = __ldcs(coord4 + 3 * g + 1);
                float4 c  = __ldcs(coord4 + 3 * g + 2);
                int4   s  = __ldcs(seg4 + g);
                if (SMEMZ) {
                    float4 zv = make_float4(packzs(a.z, s.x), packzs(bb.y, s.y),
                                            packzs(c.x, s.z), packzs(c.w, s.w));
                    *reinterpret_cast<float4*>(s_z + ((g - g0) << 2)) = zv;
                }
                int i0 = g << 2;
                float zz[4] = {a.z, bb.y, c.x, c.w};
                int   ss[4] = {s.x, s.y, s.z, s.w};
                int b = b0;
                #pragma unroll
                for (int q = 0; q < 4; q++) {
                    int i = i0 + q;
                    while (i >= s_off[b]) b++;
                    unsigned o = ordf(zz[q]);
                    atomicMax(&s_m[b], ~o);
                    atomicMax(&s_x[b], o);
                    if (ss[q]) atomicMax(&s_p[b], ~o);
                    else       atomicMax(&s_g[b], o);
                }
            }
            if (isLast) {
                for (int i = tail0 + t; i < n; i += THREADS) {
                    int b = 0; while (i >= s_off[b]) b++;
                    unsigned o = ordf(coord[3 * i + 2]);
                    atomicMax(&s_m[b], ~o);
                    atomicMax(&s_x[b], o);
                    if (segment[i]) atomicMax(&s_p[b], ~o);
                    else            atomicMax(&s_g[b], o);
                }
            }
        }
    }

    __syncthreads();
    // block -> global: at most 4*B atomics per block, typically 4
    for (int j = t; j < B; j += THREADS) {
        if (s_g[j]) atomicMax(&d_ag[j],  s_g[j]);
        if (s_p[j]) atomicMax(&d_ap[j],  s_p[j]);
        if (s_m[j]) atomicMax(&d_azm[j], s_m[j]);
        if (s_x[j]) atomicMax(&d_azx[j], s_x[j]);
    }
    __threadfence();
    __syncthreads();
    if (t == 0) {
        atomicAdd(&d_c1, 1u);
        while (atomicAdd(&d_c1, 0u) < (unsigned)NB) { __nanosleep(128); }
    }
    __syncthreads();
    __threadfence();

    // every block computes mu locally (32 L2 words)
    for (int j = t; j < B; j += THREADS) {
        unsigned ag  = __ldcg(&d_ag[j]);
        unsigned ap  = __ldcg(&d_ap[j]);
        unsigned azm = __ldcg(&d_azm[j]);
        unsigned azx = __ldcg(&d_azx[j]);
        float g = ag ? deordf(ag)  : deordf(~azm);   // gmax else zmin
        float p = ap ? deordf(~ap) : deordf(azx);    // pmin else zmax
        s_mu[j] = g + (p - g) * 0.5f;
    }
    __syncthreads();

    // ===================== phase B: focal-CE * weight, reduce =====================
    float acc = 0.0f;
    if (g0 < g1) {
        float muu = s_mu[b0];
        for (int g = g0 + t; g < g1; g += THREADS) {
            float4 pa = pred4[2 * g + 0];
            float4 pb = pred4[2 * g + 1];
            float4 zs;
            if (SMEMZ) {
                zs = *reinterpret_cast<const float4*>(s_z + ((g - g0) << 2));
            } else {
                float4 a  = coord4[3 * g + 0];
                float4 bb = coord4[3 * g + 1];
                float4 c  = coord4[3 * g + 2];
                int4   s  = seg4[g];
                zs = make_float4(packzs(a.z, s.x), packzs(bb.y, s.y),
                                 packzs(c.x, s.z), packzs(c.w, s.w));
            }
            float m0 = muu, m1 = muu, m2 = muu, m3 = muu;
            if (!uni) {
                int i0 = g << 2;
                int b = b0; while (i0 >= s_off[b]) b++;
                int q1 = b;  while (i0 + 1 >= s_off[q1]) q1++;
                int q2 = q1; while (i0 + 2 >= s_off[q2]) q2++;
                int q3 = q2; while (i0 + 3 >= s_off[q3]) q3++;
                m0 = s_mu[b]; m1 = s_mu[q1]; m2 = s_mu[q2]; m3 = s_mu[q3];
            }
            acc += pointTermZ(pa.x, pa.y, zs.x, m0);
            acc += pointTermZ(pa.z, pa.w, zs.y, m1);
            acc += pointTermZ(pb.x, pb.y, zs.z, m2);
            acc += pointTermZ(pb.z, pb.w, zs.w, m3);
        }
    }
    if (isLast && t < (n - tail0)) {
        int i = tail0 + t;
        int b = 0; while (i >= s_off[b]) b++;
        acc += pointTermZ(pred[2 * i], pred[2 * i + 1],
                          packzs(coord[3 * i + 2], segment[i]), s_mu[b]);
    }

    #pragma unroll
    for (int o = 16; o > 0; o >>= 1) acc += __shfl_xor_sync(~0u, acc, o);
    if (lane == 0) s_w[warp] = acc;
    __syncthreads();
    if (t == 0) {
        float tot = 0.0f;
        #pragma unroll
        for (int w = 0; w < NWARP; w++) tot += s_w[w];
        d_part[bid] = tot;
        __threadfence();
        s_last = (atomicAdd(&d_c2, 1u) == NB - 1);
    }
    __syncthreads();

    if (s_last) {
        // reuse s_z as double scratch (phase B done everywhere)
        double* s_d = reinterpret_cast<double*>(s_z);
        double da = 0.0;
        for (int i = t; i < NB; i += THREADS) da += (double)d_part[i];
        s_d[t] = da;
        __syncthreads();
        for (int s = THREADS / 2; s > 0; s >>= 1) {
            if (t < s) s_d[t] += s_d[t + s];
            __syncthreads();
        }
        // reset everything for next graph replay
        for (int j = t; j < B; j += THREADS) {
            d_ag[j] = 0u; d_ap[j] = 0u; d_azm[j] = 0u; d_azx[j] = 0u;
        }
        if (t == 0) {
            out[0] = (float)(s_d[0] / (double)n);
            d_c1 = 0u; d_c2 = 0u;
        }
    }
}

// ---------------- launch ----------------
extern "C" void kernel_launch(void* const* d_in, const int* in_sizes, int n_in,
                              void* d_out, int out_size)
{
    const float* pred    = (const float*)d_in[0];
    const float* coord   = (const float*)d_in[1];
    const int*   segment = (const int*)d_in[2];
    const int*   offset  = (const int*)d_in[3];
    int n = in_sizes[2];
    int B = in_sizes[3];
    if (B > MAXB) B = MAXB;
    if (B < 1) B = 1;

    int n4 = n >> 2;
    int gpb = (n4 + NB - 1) / NB;
    if (gpb < 1) gpb = 1;
    bool smemz = (gpb <= GCAP);

    if (smemz) {
        k_fused<true><<<NB, THREADS>>>((const float4*)pred, pred,
                                       (const float4*)coord, coord,
                                       (const int4*)segment, segment,
                                       offset, n, B, gpb, (float*)d_out);
    } else {
        k_fused<false><<<NB, THREADS>>>((const float4*)pred, pred,
                                        (const float4*)coord, coord,
                                        (const int4*)segment, segment,
                                        offset, n, B, gpb, (float*)d_out);
    }
}